// round 13
// baseline (speedup 1.0000x reference)
#include <cuda_runtime.h>
#include <cuda_bf16.h>
#include <cstdint>

// ---------------- problem shapes (fixed) ----------------
#define BSZ   2048
#define NIN   128
#define NHID  512
#define NOUT  128
#define NB    8
#define NF    9
#define K1    (NIN * NF)    // 1152  logical K layer1
#define K2    (NHID * NF)   // 4608  logical K layer2
#define K1E   (3 * K1)      // 3456  logical augmented K (bf16x3)
#define K2E   (3 * K2)      // 13824
#define KP1   (2 * K1)      // 2304  PHYSICAL row length (dedup: [hi|lo])
#define KP2   (2 * K2)      // 9216
#define Z1    6             // split-K slabs layer1 -> KC1 = 576 (9 chunks)
#define Z2    12            // split-K slabs layer2 -> KC2 = 1152 (18 chunks)
#define KC1   (K1E / Z1)
#define KC2   (K2E / Z2)
#define BKC   64            // K elems per smem chunk (region bounds are multiples)

// Logical K ordering (f-major, GEMM-invariant permutation):
//   k = region*Ktot + f*nIn + i, region in {0,1,2}
// A' logical regions = [hi | lo | hi], B' logical = [hi | hi | lo].
// PHYSICAL storage is deduplicated to 2 regions [hi | lo]; the GEMM remaps:
//   kA = (k >= 2*Ktot) ? k - 2*Ktot : k
//   kB = (k >=   Ktot) ? k -   Ktot : k

// ---------------- static device scratch ----------------
__device__ __nv_bfloat16 g_Wt1[(size_t)NHID * KP1];
__device__ __nv_bfloat16 g_Wt2[(size_t)NOUT * KP2];
__device__ __nv_bfloat16 g_F1 [(size_t)BSZ  * KP1];
__device__ __nv_bfloat16 g_F2 [(size_t)BSZ  * KP2];
__device__ float         g_P1 [(size_t)Z1 * BSZ * NHID];
__device__ float         g_P2 [(size_t)Z2 * BSZ * NOUT];

// ---------------- helpers ----------------
__device__ __forceinline__ uint32_t smem_u32(const void* p) {
    uint32_t a;
    asm("{ .reg .u64 t; cvta.to.shared.u64 t, %1; cvt.u32.u64 %0, t; }" : "=r"(a) : "l"(p));
    return a;
}
__device__ __forceinline__ uint32_t swz(uint32_t off) {   // SW128 swizzle
    return off ^ ((off >> 3) & 0x70);
}
__device__ __forceinline__ void cp_async16(uint32_t saddr, const void* gaddr) {
    asm volatile("cp.async.cg.shared.global [%0], [%1], 16;"
                 :: "r"(saddr), "l"(gaddr) : "memory");
}
__device__ __forceinline__ void cp_commit() {
    asm volatile("cp.async.commit_group;" ::: "memory");
}
template <int N>
__device__ __forceinline__ void cp_wait() {
    asm volatile("cp.async.wait_group %0;" :: "n"(N) : "memory");
}
__device__ __forceinline__ void ldsm_x4(uint32_t& r0, uint32_t& r1, uint32_t& r2,
                                        uint32_t& r3, uint32_t addr) {
    asm volatile("ldmatrix.sync.aligned.m8n8.x4.shared.b16 {%0,%1,%2,%3}, [%4];"
                 : "=r"(r0), "=r"(r1), "=r"(r2), "=r"(r3) : "r"(addr));
}
__device__ __forceinline__ void mma16816(float* d, const uint32_t* a, const uint32_t* b) {
    asm volatile(
        "mma.sync.aligned.m16n8k16.row.col.f32.bf16.bf16.f32 "
        "{%0,%1,%2,%3}, {%4,%5,%6,%7}, {%8,%9}, {%0,%1,%2,%3};"
        : "+f"(d[0]), "+f"(d[1]), "+f"(d[2]), "+f"(d[3])
        : "r"(a[0]), "r"(a[1]), "r"(a[2]), "r"(a[3]), "r"(b[0]), "r"(b[1]));
}

// ---------------------------------------------------------------------------
// Fold weights -> B' [N][2K] physical: hi at k, lo at Ktot+k (k = f*nIn + i).
// ---------------------------------------------------------------------------
__global__ void fold_kernel(const float* __restrict__ coef,
                            const float* __restrict__ sbase,
                            const float* __restrict__ ssp,
                            __nv_bfloat16* __restrict__ Wt,
                            int nIn, int nOut, int Ktot)
{
    int idx = blockIdx.x * blockDim.x + threadIdx.x;
    if (idx >= nIn * nOut) return;
    int o = idx / nIn;
    int i = idx - o * nIn;
    int io = i * nOut + o;
    float sb = sbase[io];
    float sp = ssp[io];
    const float* c = coef + (size_t)io * NB;
    float w[NF];
    w[0] = sb;
    #pragma unroll
    for (int f = 0; f < NB; f++) w[1 + f] = sp * c[f];

    __nv_bfloat16* row = Wt + (size_t)o * (2 * Ktot);
    #pragma unroll
    for (int f = 0; f < NF; f++) {
        float v = w[f];
        __nv_bfloat16 hi = __float2bfloat16(v);
        __nv_bfloat16 lo = __float2bfloat16(v - __bfloat162float(hi));
        int k = f * nIn + i;
        row[k]        = hi;
        row[Ktot + k] = lo;
    }
}

// ---------------------------------------------------------------------------
// Expand (optionally summing split-K slabs of x) -> A' [B][2K] physical:
// hi at k, lo at Ktot+k. Two adjacent i per thread -> coalesced bf16x2 stores.
// ---------------------------------------------------------------------------
__global__ void expand_kernel(const float* __restrict__ x, int zsum, int zstride,
                              const float* __restrict__ grid,
                              __nv_bfloat16* __restrict__ F,
                              int nIn, int Ktot, int totalPairs)
{
    int p = blockIdx.x * blockDim.x + threadIdx.x;
    if (p >= totalPairs) return;
    const int halfIn = nIn >> 1;
    int b  = p / halfIn;
    int ii = (p - b * halfIn) * 2;

    float xv[2];
    #pragma unroll
    for (int e = 0; e < 2; e++) {
        int gidx = b * nIn + ii + e;
        float v = x[gidx];
        for (int z = 1; z < zsum; z++) v += x[(size_t)z * zstride + gidx];
        xv[e] = v;
    }

    float f9[2][NF];
    #pragma unroll
    for (int e = 0; e < 2; e++) {
        const float* g = grid + (size_t)(ii + e) * 12;
        float t[12];
        #pragma unroll
        for (int j = 0; j < 12; j++) t[j] = g[j];

        float Bv[11];
        #pragma unroll
        for (int j = 0; j < 11; j++)
            Bv[j] = (xv[e] >= t[j] && xv[e] < t[j + 1]) ? 1.0f : 0.0f;
        #pragma unroll
        for (int q = 1; q <= 3; q++) {
            #pragma unroll
            for (int j = 0; j < 10; j++) {
                if (j < 11 - q) {
                    float left  = (xv[e] - t[j]) / (t[j + q] - t[j]);
                    float right = (t[j + q + 1] - xv[e]) / (t[j + q + 1] - t[j + 1]);
                    Bv[j] = left * Bv[j] + right * Bv[j + 1];
                }
            }
        }
        f9[e][0] = xv[e] / (1.0f + __expf(-xv[e]));
        #pragma unroll
        for (int f = 0; f < NB; f++) f9[e][1 + f] = Bv[f];
    }

    __nv_bfloat16* row = F + (size_t)b * (2 * Ktot);
    #pragma unroll
    for (int f = 0; f < NF; f++) {
        __nv_bfloat16 h0 = __float2bfloat16(f9[0][f]);
        __nv_bfloat16 h1 = __float2bfloat16(f9[1][f]);
        __nv_bfloat162 hi2; hi2.x = h0; hi2.y = h1;
        __nv_bfloat162 lo2;
        lo2.x = __float2bfloat16(f9[0][f] - __bfloat162float(h0));
        lo2.y = __float2bfloat16(f9[1][f] - __bfloat162float(h1));
        int k = f * nIn + ii;
        *reinterpret_cast<__nv_bfloat162*>(&row[k])        = hi2;
        *reinterpret_cast<__nv_bfloat162*>(&row[Ktot + k]) = lo2;
    }
}

// ---------------------------------------------------------------------------
// bf16 GEMM via ldmatrix + mma.sync m16n8k16.
// 128x128 tile, BK=64 double-buffered cp.async, ONE __syncthreads per chunk.
// Logical K span [0, 3*Ktot); physical rows are 2*Ktot with per-chunk remap.
//   A [Mtot][2*Ktot], B [Ntot][2*Ktot], P fp32 slabs (blockIdx.z).
// Dynamic smem: 1024 pad + 4 * 16KB = 66560 B.
// ---------------------------------------------------------------------------
__global__ void __launch_bounds__(256)
kan_mma_gemm(const __nv_bfloat16* __restrict__ A,
             const __nv_bfloat16* __restrict__ Bm,
             float* __restrict__ P, int Ntot, int KC, int partStride, int Ktot)
{
    extern __shared__ char dsm[];
    uint32_t tile = (smem_u32(dsm) + 1023u) & ~1023u;
    const uint32_t bufA[2] = { tile,           tile + 32768u };
    const uint32_t bufB[2] = { tile + 16384u,  tile + 49152u };

    const int tid  = threadIdx.x;
    const int lane = tid & 31;
    const int wid  = tid >> 5;
    const int wm   = wid & 1;        // 2 warps along M (64 rows each)
    const int wn   = wid >> 1;       // 4 warps along N (32 cols each)

    const int mrow0 = blockIdx.y * 128;
    const int ncol0 = blockIdx.x * 128;
    const int kbase = blockIdx.z * KC;
    const int nc    = KC >> 6;
    const int ldAB  = 2 * Ktot;      // physical row length (elements)

    // cooperative async tile load: 128 rows x 64 bf16 (128B rows, SW128)
    const int ld_row = tid >> 3;         // 0..31 (x4 iterations -> 128 rows)
    const int ld_ch  = (tid & 7) * 16;   // byte offset within 128B row
    auto issue_tile = [&](const __nv_bfloat16* g, int r0, int k0, uint32_t sb) {
        const char* gb = reinterpret_cast<const char*>(g) + (size_t)k0 * 2 + ld_ch;
        #pragma unroll
        for (int j = 0; j < 4; j++) {
            int row = ld_row + j * 32;
            cp_async16(sb + swz((uint32_t)(row * 128) + ld_ch),
                       gb + (size_t)(r0 + row) * ldAB * 2);
        }
    };
    // logical chunk k -> physical offsets
    auto kA = [&](int k) { return (k >= 2 * Ktot) ? k - 2 * Ktot : k; };
    auto kB = [&](int k) { return (k >= Ktot) ? k - Ktot : k; };

    float acc[4][4][4];
    #pragma unroll
    for (int mt = 0; mt < 4; mt++)
        #pragma unroll
        for (int nt = 0; nt < 4; nt++)
            #pragma unroll
            for (int e = 0; e < 4; e++) acc[mt][nt][e] = 0.0f;

    // per-lane ldmatrix address offsets (within a chunk buffer)
    const uint32_t a_row = (uint32_t)(wm * 64 + (lane & 15));
    const uint32_t a_kb  = (uint32_t)((lane >> 4) * 16);
    const uint32_t b_row = (uint32_t)(wn * 32 + ((lane & 16) >> 1) + (lane & 7));
    const uint32_t b_kb  = (uint32_t)((lane & 8) * 2);

    // prologue
    issue_tile(A,  mrow0, kA(kbase), bufA[0]);
    issue_tile(Bm, ncol0, kB(kbase), bufB[0]);
    cp_commit();

    for (int c = 0; c < nc; c++) {
        const int b = c & 1;
        cp_wait<0>();
        __syncthreads();   // buf b ready for all; all warps done reading buf b^1

        if (c + 1 < nc) {  // loads for c+1 overlap compute of c
            int kn = kbase + (c + 1) * BKC;
            issue_tile(A,  mrow0, kA(kn), bufA[b ^ 1]);
            issue_tile(Bm, ncol0, kB(kn), bufB[b ^ 1]);
            cp_commit();
        }

        const uint32_t cA = bufA[b];
        const uint32_t cB = bufB[b];
        #pragma unroll
        for (int ks = 0; ks < 4; ks++) {
            uint32_t af[4][4], bf[2][4];
            #pragma unroll
            for (int mt = 0; mt < 4; mt++)
                ldsm_x4(af[mt][0], af[mt][1], af[mt][2], af[mt][3],
                        cA + swz((a_row + mt * 16) * 128 + ks * 32 + a_kb));
            #pragma unroll
            for (int nt2 = 0; nt2 < 2; nt2++)
                ldsm_x4(bf[nt2][0], bf[nt2][1], bf[nt2][2], bf[nt2][3],
                        cB + swz((b_row + nt2 * 16) * 128 + ks * 32 + b_kb));
            #pragma unroll
            for (int mt = 0; mt < 4; mt++) {
                #pragma unroll
                for (int nt = 0; nt < 4; nt++)
                    mma16816(acc[mt][nt], af[mt], &bf[nt >> 1][(nt & 1) * 2]);
            }
        }
    }

    // epilogue: direct fp32 stores to split-K slab
    float* Pz = P + (size_t)blockIdx.z * partStride;
    const int er = lane >> 2;          // 0..7
    const int ec = (lane & 3) * 2;     // 0,2,4,6
    #pragma unroll
    for (int mt = 0; mt < 4; mt++) {
        int row = mrow0 + wm * 64 + mt * 16 + er;
        #pragma unroll
        for (int nt = 0; nt < 4; nt++) {
            int col = ncol0 + wn * 32 + nt * 8 + ec;
            float2 v0 = make_float2(acc[mt][nt][0], acc[mt][nt][1]);
            float2 v1 = make_float2(acc[mt][nt][2], acc[mt][nt][3]);
            *reinterpret_cast<float2*>(&Pz[(size_t)row * Ntot + col])       = v0;
            *reinterpret_cast<float2*>(&Pz[(size_t)(row + 8) * Ntot + col]) = v1;
        }
    }
}

// ---------------------------------------------------------------------------
// Deterministic split-K slab reduce (float4-vectorized; n % 4 == 0)
// ---------------------------------------------------------------------------
__global__ void reduce_kernel(const float* __restrict__ P, float* __restrict__ out,
                              int n, int z)
{
    int i4 = blockIdx.x * blockDim.x + threadIdx.x;
    int nq = n >> 2;
    if (i4 >= nq) return;
    float4 s = make_float4(0.f, 0.f, 0.f, 0.f);
    for (int j = 0; j < z; j++) {
        float4 v = *reinterpret_cast<const float4*>(&P[(size_t)j * n + i4 * 4]);
        s.x += v.x; s.y += v.y; s.z += v.z; s.w += v.w;
    }
    *reinterpret_cast<float4*>(&out[i4 * 4]) = s;
}

// ---------------------------------------------------------------------------
extern "C" void kernel_launch(void* const* d_in, const int* in_sizes, int n_in,
                              void* d_out, int out_size)
{
    const float* state = (const float*)d_in[0];
    const float* grid1 = (const float*)d_in[1];
    const float* coef1 = (const float*)d_in[2];
    const float* sb1   = (const float*)d_in[3];
    const float* sp1   = (const float*)d_in[4];
    const float* grid2 = (const float*)d_in[5];
    const float* coef2 = (const float*)d_in[6];
    const float* sb2   = (const float*)d_in[7];
    const float* sp2   = (const float*)d_in[8];
    float* out = (float*)d_out;

    __nv_bfloat16 *Wt1, *Wt2, *F1, *F2;
    float *P1, *P2;
    cudaGetSymbolAddress((void**)&Wt1, g_Wt1);
    cudaGetSymbolAddress((void**)&Wt2, g_Wt2);
    cudaGetSymbolAddress((void**)&F1,  g_F1);
    cudaGetSymbolAddress((void**)&F2,  g_F2);
    cudaGetSymbolAddress((void**)&P1,  g_P1);
    cudaGetSymbolAddress((void**)&P2,  g_P2);

    const int GEMM_SMEM = 66560;   // 1024 pad + 64KB double-buffered tiles
    cudaFuncSetAttribute(kan_mma_gemm, cudaFuncAttributeMaxDynamicSharedMemorySize,
                         GEMM_SMEM);

    // fold weights (independent of data path)
    fold_kernel<<<(NIN * NHID + 255) / 256, 256>>>(coef1, sb1, sp1, Wt1, NIN, NHID, K1);
    fold_kernel<<<(NHID * NOUT + 255) / 256, 256>>>(coef2, sb2, sp2, Wt2, NHID, NOUT, K2);

    // layer 1
    {
        int pairs = BSZ * NIN / 2;
        expand_kernel<<<(pairs + 255) / 256, 256>>>(state, 1, 0, grid1, F1, NIN, K1, pairs);
    }
    kan_mma_gemm<<<dim3(NHID / 128, BSZ / 128, Z1), 256, GEMM_SMEM>>>(
        F1, Wt1, P1, NHID, KC1, BSZ * NHID, K1);

    // layer 2 (expand fuses the slab reduction of P1)
    {
        int pairs = BSZ * NHID / 2;
        expand_kernel<<<(pairs + 255) / 256, 256>>>(P1, Z1, BSZ * NHID, grid2, F2,
                                                    NHID, K2, pairs);
    }
    kan_mma_gemm<<<dim3(NOUT / 128, BSZ / 128, Z2), 256, GEMM_SMEM>>>(
        F2, Wt2, P2, NOUT, KC2, BSZ * NOUT, K2);

    reduce_kernel<<<(BSZ * NOUT / 4 + 255) / 256, 256>>>(P2, out, BSZ * NOUT, Z2);
}